// round 12
// baseline (speedup 1.0000x reference)
#include <cuda_runtime.h>
#include <cuda_bf16.h>
#include <cstdint>

#define NN 50000
#define EE 200000
#define IND 768
#define HIDD 256
#define OUTD 64
#define NHEAD 4
#define DH 64
#define RELS 6
#define NEG 0.2f
#define LNEPS 1e-5f

// ---------------- scratch (static device globals; no allocs) ----------------
__device__ float g_h1[(size_t)NN * HIDD];     // x_mod @ W1
__device__ float g_agg1[(size_t)NN * HIDD];   // layer1 aggregation, then LN+ELU in place
__device__ float g_embW1[RELS * HIDD];        // edge_emb @ W1
__device__ int   g_winner[NN];                // last edge id with src==node, else -1
__device__ float g_als1[NN * NHEAD], g_ald1[NN * NHEAD];
__device__ unsigned g_emax1[NN * NHEAD];
__device__ float g_denom1[NN * NHEAD];
__device__ float g_ex1[(size_t)EE * NHEAD];
__device__ float g_z[(size_t)NN * OUTD];      // h2 @ W2
__device__ float g_als2[NN], g_ald2[NN];
__device__ unsigned g_emax2[NN];
__device__ float g_denom2[NN];
__device__ float g_ex2[EE];
// converted edge arrays (int32), robust to int32/int64 input dtype
__device__ int g_src[EE], g_dst[EE], g_et[EE];
__device__ int g_is64;                         // 1 if inputs are int64

// ---------------- helpers ----------------
__device__ __forceinline__ unsigned fkey(float f) {
    unsigned b = __float_as_uint(f);
    return (b & 0x80000000u) ? ~b : (b | 0x80000000u);
}
__device__ __forceinline__ float funkey(unsigned k) {
    unsigned b = (k & 0x80000000u) ? (k & 0x7FFFFFFFu) : ~k;
    return __uint_as_float(b);
}
__device__ __forceinline__ unsigned pack_hi2(float a, float b) {
    unsigned la = (unsigned)__bfloat16_as_ushort(__float2bfloat16_rn(a));
    unsigned lb = (unsigned)__bfloat16_as_ushort(__float2bfloat16_rn(b));
    return la | (lb << 16);
}
__device__ __forceinline__ unsigned pack_lo2(float a, float b) {
    float ra = a - __bfloat162float(__float2bfloat16_rn(a));
    float rb = b - __bfloat162float(__float2bfloat16_rn(b));
    unsigned la = (unsigned)__bfloat16_as_ushort(__float2bfloat16_rn(ra));
    unsigned lb = (unsigned)__bfloat16_as_ushort(__float2bfloat16_rn(rb));
    return la | (lb << 16);
}
__device__ __forceinline__ void mma16816(float* c, const uint32_t* a, uint32_t b0, uint32_t b1) {
    asm volatile(
        "mma.sync.aligned.m16n8k16.row.col.f32.bf16.bf16.f32 "
        "{%0,%1,%2,%3}, {%4,%5,%6,%7}, {%8,%9}, {%0,%1,%2,%3};"
        : "+f"(c[0]), "+f"(c[1]), "+f"(c[2]), "+f"(c[3])
        : "r"(a[0]), "r"(a[1]), "r"(a[2]), "r"(a[3]), "r"(b0), "r"(b1));
}

// ---------------- dtype detect + convert ----------------
__global__ void k_detect(const int* __restrict__ ei32) {
    __shared__ int any_nz;
    if (threadIdx.x == 0) any_nz = 0;
    __syncthreads();
    if (ei32[2 * threadIdx.x + 1] != 0) atomicOr(&any_nz, 1);
    __syncthreads();
    if (threadIdx.x == 0) g_is64 = (any_nz == 0) ? 1 : 0;
}

__global__ void k_convert(const int* __restrict__ ei32, const int* __restrict__ et32) {
    int e = blockIdx.x * blockDim.x + threadIdx.x;
    if (e >= EE) return;
    if (g_is64) {
        g_src[e] = ei32[2 * e];
        g_dst[e] = ei32[2 * (EE + e)];
        g_et[e]  = et32[2 * e];
    } else {
        g_src[e] = ei32[e];
        g_dst[e] = ei32[EE + e];
        g_et[e]  = et32[e];
    }
}

// ---------------- init ----------------
__global__ void k_init(float* __restrict__ out) {
    size_t i = (size_t)blockIdx.x * blockDim.x + threadIdx.x;
    if (i < (size_t)NN * HIDD) g_agg1[i] = 0.f;
    if (i < (size_t)NN * OUTD) out[i] = 0.f;
    if (i < NN * NHEAD) { g_denom1[i] = 0.f; g_emax1[i] = 0u; }
    if (i < NN) { g_winner[i] = -1; g_denom2[i] = 0.f; g_emax2[i] = 0u; }
}

__global__ void k_winner() {
    int e = blockIdx.x * blockDim.x + threadIdx.x;
    if (e >= EE) return;
    atomicMax(&g_winner[g_src[e]], e);
}

// edge_emb @ W1 -> [RELS, HIDD]  (fp32, exact)
__global__ void k_embw(const float* __restrict__ emb, const float* __restrict__ W1) {
    int r = blockIdx.x, c = threadIdx.x;
    float s = 0.f;
#pragma unroll 8
    for (int k = 0; k < IND; k++) s += emb[r * IND + k] * W1[(size_t)k * HIDD + c];
    g_embW1[r * HIDD + c] = s;
}

// ---------------- GEMM1 via warp mma.sync bf16-split (HMMA) ----------------
// h1 = x@W1 (+ winner delta). 3-term: xhi*whi + xlo*whi + xhi*wlo, fp32 acc.
// CTA 128x128, 8 warps (warp tile 32x64), K tiles of 32, register prefetch.
#define KP 40   // bf16 k-stride (80B rows: conflict-free fragment quads)

__global__ __launch_bounds__(256)
void k_gemm1_mma(const float* __restrict__ A, const float* __restrict__ B) {
    __shared__ __align__(16) __nv_bfloat16 sAhi[128][KP];
    __shared__ __align__(16) __nv_bfloat16 sAlo[128][KP];
    __shared__ __align__(16) __nv_bfloat16 sBhi[128][KP];
    __shared__ __align__(16) __nv_bfloat16 sBlo[128][KP];

    const int tid = threadIdx.x;
    const int wid = tid >> 5, lane = tid & 31;
    const int qr = lane >> 2, qc = lane & 3;
    const int wm = (wid & 3) * 32;          // warp M offset in tile
    const int wn = (wid >> 2) * 64;         // warp N offset in tile
    const int bm = blockIdx.x * 128;
    const int bn = blockIdx.y * 128;

    float acc[2][8][4];
#pragma unroll
    for (int i = 0; i < 2; i++)
#pragma unroll
        for (int j = 0; j < 8; j++)
#pragma unroll
            for (int r = 0; r < 4; r++) acc[i][j][r] = 0.f;

    float4 pa[4], pb[4];
    // prologue: fetch k-tile 0
#pragma unroll
    for (int i = 0; i < 4; i++) {
        int idx = tid + 256 * i;
        int row = idx >> 3, col = (idx & 7) * 4;           // A: 128 x 32
        int gr = bm + row;
        pa[i] = make_float4(0.f, 0.f, 0.f, 0.f);
        if (gr < NN) pa[i] = *(const float4*)&A[(size_t)gr * IND + col];
        int kr = idx >> 5, nc = (idx & 31) * 4;            // B: 32 x 128
        pb[i] = *(const float4*)&B[(size_t)kr * HIDD + bn + nc];
    }

    for (int kt = 0; kt < 24; kt++) {
        // store prefetched tile to SMEM (hi/lo split)
#pragma unroll
        for (int i = 0; i < 4; i++) {
            int idx = tid + 256 * i;
            int row = idx >> 3, col = (idx & 7) * 4;
            float4 v = pa[i];
            *(uint2*)&sAhi[row][col] = make_uint2(pack_hi2(v.x, v.y), pack_hi2(v.z, v.w));
            *(uint2*)&sAlo[row][col] = make_uint2(pack_lo2(v.x, v.y), pack_lo2(v.z, v.w));
            int kr = idx >> 5, nc = (idx & 31) * 4;
            float4 w = pb[i];
            float ws[4] = {w.x, w.y, w.z, w.w};
#pragma unroll
            for (int u = 0; u < 4; u++) {
                __nv_bfloat16 hi = __float2bfloat16_rn(ws[u]);
                sBhi[nc + u][kr] = hi;
                sBlo[nc + u][kr] = __float2bfloat16_rn(ws[u] - __bfloat162float(hi));
            }
        }
        __syncthreads();
        // prefetch next k-tile
        if (kt < 23) {
            int k0 = (kt + 1) * 32;
#pragma unroll
            for (int i = 0; i < 4; i++) {
                int idx = tid + 256 * i;
                int row = idx >> 3, col = (idx & 7) * 4;
                int gr = bm + row;
                pa[i] = make_float4(0.f, 0.f, 0.f, 0.f);
                if (gr < NN) pa[i] = *(const float4*)&A[(size_t)gr * IND + k0 + col];
                int kr = idx >> 5, nc = (idx & 31) * 4;
                pb[i] = *(const float4*)&B[(size_t)(k0 + kr) * HIDD + bn + nc];
            }
        }
        // compute: 2 k16 steps
#pragma unroll
        for (int ks = 0; ks < 32; ks += 16) {
            uint32_t ahi[2][4], alo[2][4];
#pragma unroll
            for (int i = 0; i < 2; i++) {
                int r0 = wm + i * 16 + qr;
                int kc = ks + qc * 2;
                ahi[i][0] = *(const uint32_t*)&sAhi[r0][kc];
                ahi[i][1] = *(const uint32_t*)&sAhi[r0 + 8][kc];
                ahi[i][2] = *(const uint32_t*)&sAhi[r0][kc + 8];
                ahi[i][3] = *(const uint32_t*)&sAhi[r0 + 8][kc + 8];
                alo[i][0] = *(const uint32_t*)&sAlo[r0][kc];
                alo[i][1] = *(const uint32_t*)&sAlo[r0 + 8][kc];
                alo[i][2] = *(const uint32_t*)&sAlo[r0][kc + 8];
                alo[i][3] = *(const uint32_t*)&sAlo[r0 + 8][kc + 8];
            }
#pragma unroll
            for (int j = 0; j < 8; j++) {
                int n0 = wn + j * 8 + qr;
                int kc = ks + qc * 2;
                uint32_t bh0 = *(const uint32_t*)&sBhi[n0][kc];
                uint32_t bh1 = *(const uint32_t*)&sBhi[n0][kc + 8];
                uint32_t bl0 = *(const uint32_t*)&sBlo[n0][kc];
                uint32_t bl1 = *(const uint32_t*)&sBlo[n0][kc + 8];
#pragma unroll
                for (int i = 0; i < 2; i++) {
                    mma16816(acc[i][j], ahi[i], bh0, bh1);
                    mma16816(acc[i][j], alo[i], bh0, bh1);
                    mma16816(acc[i][j], ahi[i], bl0, bl1);
                }
            }
        }
        __syncthreads();
    }

    // epilogue: write g_h1 with winner delta fused
#pragma unroll
    for (int i = 0; i < 2; i++) {
#pragma unroll
        for (int half = 0; half < 2; half++) {
            int gr = bm + wm + i * 16 + qr + half * 8;
            if (gr >= NN) continue;
            int w = g_winner[gr];
            int t = (w >= 0) ? g_et[w] : -1;
#pragma unroll
            for (int j = 0; j < 8; j++) {
                int col = bn + wn + j * 8 + qc * 2;
                float2 v;
                v.x = acc[i][j][half * 2 + 0];
                v.y = acc[i][j][half * 2 + 1];
                if (t >= 0) {
                    v.x += g_embW1[t * HIDD + col];
                    v.y += g_embW1[t * HIDD + col + 1];
                }
                *(float2*)&g_h1[(size_t)gr * HIDD + col] = v;
            }
        }
    }
}

// ---------------- layer 1 attention ----------------
__global__ void k_logits1(const float* __restrict__ as1, const float* __restrict__ ad1) {
    int n = blockIdx.x;
    int h = threadIdx.x >> 5, l = threadIdx.x & 31;
    float v0 = g_h1[(size_t)n * HIDD + h * DH + l];
    float v1 = g_h1[(size_t)n * HIDD + h * DH + 32 + l];
    float s = v0 * as1[h * DH + l] + v1 * as1[h * DH + 32 + l];
    float d = v0 * ad1[h * DH + l] + v1 * ad1[h * DH + 32 + l];
#pragma unroll
    for (int o = 16; o; o >>= 1) {
        s += __shfl_xor_sync(0xffffffffu, s, o);
        d += __shfl_xor_sync(0xffffffffu, d, o);
    }
    if (l == 0) { g_als1[n * NHEAD + h] = s; g_ald1[n * NHEAD + h] = d; }
}

__global__ void k_max1() {
    int idx = blockIdx.x * blockDim.x + threadIdx.x;
    if (idx >= EE * NHEAD) return;
    int e = idx >> 2, h = idx & 3;
    int s = g_src[e], d = g_dst[e];
    float ev = g_als1[s * NHEAD + h] + g_ald1[d * NHEAD + h];
    ev = (ev >= 0.f) ? ev : NEG * ev;
    atomicMax(&g_emax1[d * NHEAD + h], fkey(ev));
}

__global__ void k_sum1() {
    int idx = blockIdx.x * blockDim.x + threadIdx.x;
    if (idx >= EE * NHEAD) return;
    int e = idx >> 2, h = idx & 3;
    int s = g_src[e], d = g_dst[e];
    float ev = g_als1[s * NHEAD + h] + g_ald1[d * NHEAD + h];
    ev = (ev >= 0.f) ? ev : NEG * ev;
    float ex = expf(ev - funkey(g_emax1[d * NHEAD + h]));
    atomicAdd(&g_denom1[d * NHEAD + h], ex);
    g_ex1[(size_t)e * NHEAD + h] = ex;
}

// block (256 threads) per edge: agg1[dst] += h1[src] * alpha
__global__ void k_agg1() {
    int e = blockIdx.x;
    __shared__ float al[NHEAD];
    int ss = g_src[e], dd = g_dst[e];
    if (threadIdx.x < NHEAD)
        al[threadIdx.x] = g_ex1[(size_t)e * NHEAD + threadIdx.x] /
                          g_denom1[dd * NHEAD + threadIdx.x];
    __syncthreads();
    int f = threadIdx.x;
    atomicAdd(&g_agg1[(size_t)dd * HIDD + f], g_h1[(size_t)ss * HIDD + f] * al[f >> 6]);
}

// warp per node: +b1, LayerNorm, ELU (in place on g_agg1)
__global__ void k_ln1(const float* __restrict__ b1, const float* __restrict__ g1,
                      const float* __restrict__ be1) {
    int n = blockIdx.x * 4 + (threadIdx.x >> 5);
    if (n >= NN) return;
    int l = threadIdx.x & 31;
    float v[8]; float sum = 0.f;
#pragma unroll
    for (int i = 0; i < 8; i++) {
        v[i] = g_agg1[(size_t)n * HIDD + i * 32 + l] + b1[i * 32 + l];
        sum += v[i];
    }
#pragma unroll
    for (int o = 16; o; o >>= 1) sum += __shfl_xor_sync(0xffffffffu, sum, o);
    float mu = sum * (1.f / HIDD);
    float s2 = 0.f;
#pragma unroll
    for (int i = 0; i < 8; i++) { v[i] -= mu; s2 += v[i] * v[i]; }
#pragma unroll
    for (int o = 16; o; o >>= 1) s2 += __shfl_xor_sync(0xffffffffu, s2, o);
    float r = rsqrtf(s2 * (1.f / HIDD) + LNEPS);
#pragma unroll
    for (int i = 0; i < 8; i++) {
        float y = v[i] * r * g1[i * 32 + l] + be1[i * 32 + l];
        g_agg1[(size_t)n * HIDD + i * 32 + l] = (y > 0.f) ? y : expm1f(y);
    }
}

// ---------------- GEMM2: z = h2 @ W2  (128x64 tile, BK=16) ----------------
__global__ __launch_bounds__(256, 2)
void k_gemm2(const float* __restrict__ B) {
    __shared__ float As[16][128];
    __shared__ float Bs[16][64];
    const float* A = g_agg1;
    const int tid = threadIdx.x;
    const int tx = tid & 15, ty = tid >> 4;
    const int bm = blockIdx.y * 128;

    float acc[8][4];
#pragma unroll
    for (int m = 0; m < 8; m++)
#pragma unroll
        for (int j = 0; j < 4; j++) acc[m][j] = 0.f;

    float4 pa[2], pb;
#pragma unroll
    for (int i = 0; i < 2; i++) {
        int s = tid * 2 + i;
        int row = s >> 2, kc = (s & 3) * 4;
        int gr = bm + row;
        pa[i] = make_float4(0.f, 0.f, 0.f, 0.f);
        if (gr < NN) pa[i] = *(const float4*)&A[(size_t)gr * HIDD + kc];
    }
    { int kr = tid >> 4, nc = (tid & 15) * 4;
      pb = *(const float4*)&B[(size_t)kr * OUTD + nc]; }
#pragma unroll
    for (int i = 0; i < 2; i++) {
        int s = tid * 2 + i;
        int row = s >> 2, kc = (s & 3) * 4;
        As[kc + 0][row] = pa[i].x; As[kc + 1][row] = pa[i].y;
        As[kc + 2][row] = pa[i].z; As[kc + 3][row] = pa[i].w;
    }
    { int kr = tid >> 4, nc = (tid & 15) * 4; *(float4*)&Bs[kr][nc] = pb; }
    __syncthreads();

    for (int kt = 0; kt < 16; kt++) {
        if (kt < 15) {
            int k0 = (kt + 1) * 16;
#pragma unroll
            for (int i = 0; i < 2; i++) {
                int s = tid * 2 + i;
                int row = s >> 2, kc = (s & 3) * 4;
                int gr = bm + row;
                pa[i] = make_float4(0.f, 0.f, 0.f, 0.f);
                if (gr < NN) pa[i] = *(const float4*)&A[(size_t)gr * HIDD + k0 + kc];
            }
            { int kr = tid >> 4, nc = (tid & 15) * 4;
              pb = *(const float4*)&B[(size_t)(k0 + kr) * OUTD + nc]; }
        }
#pragma unroll
        for (int k = 0; k < 16; k++) {
            float4 b0 = *(const float4*)&Bs[k][tx * 4];
            float4 a0 = *(const float4*)&As[k][ty * 8];
            float4 a1 = *(const float4*)&As[k][ty * 8 + 4];
            float av[8] = {a0.x, a0.y, a0.z, a0.w, a1.x, a1.y, a1.z, a1.w};
            float bv[4] = {b0.x, b0.y, b0.z, b0.w};
#pragma unroll
            for (int m = 0; m < 8; m++)
#pragma unroll
                for (int j = 0; j < 4; j++)
                    acc[m][j] = fmaf(av[m], bv[j], acc[m][j]);
        }
        __syncthreads();
        if (kt < 15) {
#pragma unroll
            for (int i = 0; i < 2; i++) {
                int s = tid * 2 + i;
                int row = s >> 2, kc = (s & 3) * 4;
                As[kc + 0][row] = pa[i].x; As[kc + 1][row] = pa[i].y;
                As[kc + 2][row] = pa[i].z; As[kc + 3][row] = pa[i].w;
            }
            { int kr = tid >> 4, nc = (tid & 15) * 4; *(float4*)&Bs[kr][nc] = pb; }
        }
        __syncthreads();
    }

#pragma unroll
    for (int m = 0; m < 8; m++) {
        int gr = bm + ty * 8 + m;
        if (gr >= NN) continue;
        float4 v = make_float4(acc[m][0], acc[m][1], acc[m][2], acc[m][3]);
        *(float4*)&g_z[(size_t)gr * OUTD + tx * 4] = v;
    }
}

// ---------------- layer 2 attention ----------------
__global__ void k_logits2(const float* __restrict__ as2, const float* __restrict__ ad2) {
    int n = blockIdx.x * 4 + (threadIdx.x >> 5);
    if (n >= NN) return;
    int l = threadIdx.x & 31;
    float v0 = g_z[(size_t)n * OUTD + l];
    float v1 = g_z[(size_t)n * OUTD + 32 + l];
    float s = v0 * as2[l] + v1 * as2[32 + l];
    float d = v0 * ad2[l] + v1 * ad2[32 + l];
#pragma unroll
    for (int o = 16; o; o >>= 1) {
        s += __shfl_xor_sync(0xffffffffu, s, o);
        d += __shfl_xor_sync(0xffffffffu, d, o);
    }
    if (l == 0) { g_als2[n] = s; g_ald2[n] = d; }
}

__global__ void k_max2() {
    int e = blockIdx.x * blockDim.x + threadIdx.x;
    if (e >= EE) return;
    int s = g_src[e], d = g_dst[e];
    float ev = g_als2[s] + g_ald2[d];
    ev = (ev >= 0.f) ? ev : NEG * ev;
    atomicMax(&g_emax2[d], fkey(ev));
}

__global__ void k_sum2() {
    int e = blockIdx.x * blockDim.x + threadIdx.x;
    if (e >= EE) return;
    int s = g_src[e], d = g_dst[e];
    float ev = g_als2[s] + g_ald2[d];
    ev = (ev >= 0.f) ? ev : NEG * ev;
    float ex = expf(ev - funkey(g_emax2[d]));
    atomicAdd(&g_denom2[d], ex);
    g_ex2[e] = ex;
}

__global__ void k_agg2(float* __restrict__ out) {
    int idx = blockIdx.x * blockDim.x + threadIdx.x;
    if (idx >= EE * OUTD) return;
    int e = idx >> 6, f = idx & 63;
    int s = g_src[e], d = g_dst[e];
    float alpha = g_ex2[e] / g_denom2[d];
    atomicAdd(&out[(size_t)d * OUTD + f], g_z[(size_t)s * OUTD + f] * alpha);
}

// warp per node: +b2, LayerNorm -> final out (in place)
__global__ void k_ln2(const float* __restrict__ b2, const float* __restrict__ g2,
                      const float* __restrict__ be2, float* __restrict__ out) {
    int n = blockIdx.x * 4 + (threadIdx.x >> 5);
    if (n >= NN) return;
    int l = threadIdx.x & 31;
    float v0 = out[(size_t)n * OUTD + l] + b2[l];
    float v1 = out[(size_t)n * OUTD + 32 + l] + b2[32 + l];
    float sum = v0 + v1;
#pragma unroll
    for (int o = 16; o; o >>= 1) sum += __shfl_xor_sync(0xffffffffu, sum, o);
    float mu = sum * (1.f / OUTD);
    v0 -= mu; v1 -= mu;
    float s2 = v0 * v0 + v1 * v1;
#pragma unroll
    for (int o = 16; o; o >>= 1) s2 += __shfl_xor_sync(0xffffffffu, s2, o);
    float r = rsqrtf(s2 * (1.f / OUTD) + LNEPS);
    out[(size_t)n * OUTD + l]      = v0 * r * g2[l] + be2[l];
    out[(size_t)n * OUTD + 32 + l] = v1 * r * g2[32 + l] + be2[32 + l];
}

// ---------------- launch ----------------
extern "C" void kernel_launch(void* const* d_in, const int* in_sizes, int n_in,
                              void* d_out, int out_size) {
    const float* x   = (const float*)d_in[0];
    const int*   ei  = (const int*)d_in[1];   // int32 or int64 (auto-detected)
    const int*   et  = (const int*)d_in[2];
    const float* emb = (const float*)d_in[3];
    const float* W1  = (const float*)d_in[4];
    const float* as1 = (const float*)d_in[5];
    const float* ad1 = (const float*)d_in[6];
    const float* b1  = (const float*)d_in[7];
    const float* g1  = (const float*)d_in[8];
    const float* be1 = (const float*)d_in[9];
    const float* W2  = (const float*)d_in[10];
    const float* as2 = (const float*)d_in[11];
    const float* ad2 = (const float*)d_in[12];
    const float* b2  = (const float*)d_in[13];
    const float* g2  = (const float*)d_in[14];
    const float* be2 = (const float*)d_in[15];
    float* out = (float*)d_out;

    k_detect<<<1, 256>>>(ei);
    k_convert<<<(EE + 255) / 256, 256>>>(ei, et);
    k_init<<<(NN * HIDD + 255) / 256, 256>>>(out);
    k_winner<<<(EE + 255) / 256, 256>>>();
    k_embw<<<RELS, HIDD>>>(emb, W1);

    dim3 grid1((NN + 127) / 128, 2);
    k_gemm1_mma<<<grid1, 256>>>(x, W1);

    k_logits1<<<NN, 128>>>(as1, ad1);
    k_max1<<<(EE * NHEAD + 255) / 256, 256>>>();
    k_sum1<<<(EE * NHEAD + 255) / 256, 256>>>();
    k_agg1<<<EE, HIDD>>>();
    k_ln1<<<(NN + 3) / 4, 128>>>(b1, g1, be1);

    dim3 grid2(1, (NN + 127) / 128);
    k_gemm2<<<grid2, 256>>>(W2);

    k_logits2<<<(NN + 3) / 4, 128>>>(as2, ad2);
    k_max2<<<(EE + 255) / 256, 256>>>();
    k_sum2<<<(EE + 255) / 256, 256>>>();
    k_agg2<<<(EE * OUTD + 255) / 256, 256>>>(out);
    k_ln2<<<(NN + 3) / 4, 128>>>(b2, g2, be2, out);
}

// round 13
// speedup vs baseline: 1.1904x; 1.1904x over previous
#include <cuda_runtime.h>
#include <cuda_bf16.h>
#include <cstdint>

#define NN 50000
#define EE 200000
#define IND 768
#define HIDD 256
#define OUTD 64
#define NHEAD 4
#define DH 64
#define RELS 6
#define NEG 0.2f
#define LNEPS 1e-5f

// ---------------- scratch (static device globals; no allocs) ----------------
__device__ float g_h1[(size_t)NN * HIDD];     // x_mod @ W1
__device__ float g_agg1[(size_t)NN * HIDD];   // layer1 LN+ELU output
__device__ float g_embW1[RELS * HIDD];        // edge_emb @ W1
__device__ int   g_winner[NN];                // last edge id with src==node, else -1
__device__ float g_als1[NN * NHEAD], g_ald1[NN * NHEAD];
__device__ float g_z[(size_t)NN * OUTD];      // h2 @ W2
__device__ float g_als2[NN], g_ald2[NN];
// edge arrays (int32) + CSR by dst
__device__ int g_src[EE], g_dst[EE], g_et[EE];
__device__ int g_deg[NN], g_cur[NN];
__device__ int g_off[NN + 1];
__device__ int g_esrc[EE];                    // src node per CSR slot
__device__ int g_is64;

// ---------------- init (+ embW1 fused on first RELS blocks) ----------------
__global__ void k_init_embw(const float* __restrict__ emb, const float* __restrict__ W1) {
    int i = blockIdx.x * blockDim.x + threadIdx.x;
    if (i < NN) { g_winner[i] = -1; g_deg[i] = 0; g_cur[i] = 0; }
    if (blockIdx.x < RELS) {
        int r = blockIdx.x, c = threadIdx.x;
        float s = 0.f;
#pragma unroll 8
        for (int k = 0; k < IND; k++) s += emb[r * IND + k] * W1[(size_t)k * HIDD + c];
        g_embW1[r * HIDD + c] = s;
    }
}

// ---------------- dtype detect ----------------
__global__ void k_detect(const int* __restrict__ ei32) {
    __shared__ int any_nz;
    if (threadIdx.x == 0) any_nz = 0;
    __syncthreads();
    if (ei32[2 * threadIdx.x + 1] != 0) atomicOr(&any_nz, 1);
    __syncthreads();
    if (threadIdx.x == 0) g_is64 = (any_nz == 0) ? 1 : 0;
}

// ---------------- convert + winner + degree count (fused) ----------------
__global__ void k_convwc(const int* __restrict__ ei32, const int* __restrict__ et32) {
    int e = blockIdx.x * blockDim.x + threadIdx.x;
    if (e >= EE) return;
    int s, d, t;
    if (g_is64) { s = ei32[2 * e]; d = ei32[2 * (EE + e)]; t = et32[2 * e]; }
    else        { s = ei32[e];     d = ei32[EE + e];       t = et32[e]; }
    g_src[e] = s; g_dst[e] = d; g_et[e] = t;
    atomicMax(&g_winner[s], e);
    atomicAdd(&g_deg[d], 1);
}

// ---------------- GEMM1: h1 = x @ W1 (+ winner delta), FFMA 128x128 ----------------
__global__ __launch_bounds__(256, 2)
void k_gemm1(const float* __restrict__ A, const float* __restrict__ B) {
    __shared__ float As[16][128];
    __shared__ float Bs[16][128];
    const int tid = threadIdx.x;
    const int tx = tid & 15, ty = tid >> 4;
    const int bm = blockIdx.y * 128, bn = blockIdx.x * 128;

    float acc[8][8];
#pragma unroll
    for (int m = 0; m < 8; m++)
#pragma unroll
        for (int j = 0; j < 8; j++) acc[m][j] = 0.f;

    float4 pa[2], pb[2];
#pragma unroll
    for (int i = 0; i < 2; i++) {
        int s = tid * 2 + i;
        int row = s >> 2, kc = (s & 3) * 4;
        int gr = bm + row;
        pa[i] = make_float4(0.f, 0.f, 0.f, 0.f);
        if (gr < NN) pa[i] = *(const float4*)&A[(size_t)gr * IND + kc];
        int kr = s >> 5, nc = (s & 31) * 4;
        pb[i] = *(const float4*)&B[(size_t)kr * HIDD + bn + nc];
    }
#pragma unroll
    for (int i = 0; i < 2; i++) {
        int s = tid * 2 + i;
        int row = s >> 2, kc = (s & 3) * 4;
        As[kc + 0][row] = pa[i].x; As[kc + 1][row] = pa[i].y;
        As[kc + 2][row] = pa[i].z; As[kc + 3][row] = pa[i].w;
        int kr = s >> 5, nc = (s & 31) * 4;
        *(float4*)&Bs[kr][nc] = pb[i];
    }
    __syncthreads();

    for (int kt = 0; kt < 48; kt++) {
        if (kt < 47) {
            int k0 = (kt + 1) * 16;
#pragma unroll
            for (int i = 0; i < 2; i++) {
                int s = tid * 2 + i;
                int row = s >> 2, kc = (s & 3) * 4;
                int gr = bm + row;
                pa[i] = make_float4(0.f, 0.f, 0.f, 0.f);
                if (gr < NN) pa[i] = *(const float4*)&A[(size_t)gr * IND + k0 + kc];
                int kr = s >> 5, nc = (s & 31) * 4;
                pb[i] = *(const float4*)&B[(size_t)(k0 + kr) * HIDD + bn + nc];
            }
        }
#pragma unroll
        for (int k = 0; k < 16; k++) {
            float4 b0 = *(const float4*)&Bs[k][tx * 8];
            float4 b1 = *(const float4*)&Bs[k][tx * 8 + 4];
            float4 a0 = *(const float4*)&As[k][ty * 8];
            float4 a1 = *(const float4*)&As[k][ty * 8 + 4];
            float av[8] = {a0.x, a0.y, a0.z, a0.w, a1.x, a1.y, a1.z, a1.w};
            float bv[8] = {b0.x, b0.y, b0.z, b0.w, b1.x, b1.y, b1.z, b1.w};
#pragma unroll
            for (int m = 0; m < 8; m++)
#pragma unroll
                for (int j = 0; j < 8; j++)
                    acc[m][j] = fmaf(av[m], bv[j], acc[m][j]);
        }
        __syncthreads();
        if (kt < 47) {
#pragma unroll
            for (int i = 0; i < 2; i++) {
                int s = tid * 2 + i;
                int row = s >> 2, kc = (s & 3) * 4;
                As[kc + 0][row] = pa[i].x; As[kc + 1][row] = pa[i].y;
                As[kc + 2][row] = pa[i].z; As[kc + 3][row] = pa[i].w;
                int kr = s >> 5, nc = (s & 31) * 4;
                *(float4*)&Bs[kr][nc] = pb[i];
            }
        }
        __syncthreads();
    }

#pragma unroll
    for (int m = 0; m < 8; m++) {
        int gr = bm + ty * 8 + m;
        if (gr >= NN) continue;
        int w = g_winner[gr];
        int t = (w >= 0) ? g_et[w] : -1;
#pragma unroll
        for (int j = 0; j < 8; j++) {
            int col = bn + tx * 8 + j;
            float v = acc[m][j];
            if (t >= 0) v += g_embW1[t * HIDD + col];
            g_h1[(size_t)gr * HIDD + col] = v;
        }
    }
}

// ---------------- CSR build: single-block scan + fill ----------------
__global__ void k_scan() {
    __shared__ int wsum[32];
    __shared__ int carry_s;
    int tid = threadIdx.x;
    if (tid == 0) carry_s = 0;
    __syncthreads();
    for (int base = 0; base < NN; base += 1024) {
        int i = base + tid;
        int v = (i < NN) ? g_deg[i] : 0;
        int x = v;
#pragma unroll
        for (int o = 1; o < 32; o <<= 1) {
            int y = __shfl_up_sync(0xffffffffu, x, o);
            if ((tid & 31) >= o) x += y;
        }
        if ((tid & 31) == 31) wsum[tid >> 5] = x;
        __syncthreads();
        if (tid < 32) {
            int s = wsum[tid];
#pragma unroll
            for (int o = 1; o < 32; o <<= 1) {
                int y = __shfl_up_sync(0xffffffffu, s, o);
                if (tid >= o) s += y;
            }
            wsum[tid] = s;
        }
        __syncthreads();
        int pre = (tid >= 32) ? wsum[(tid >> 5) - 1] : 0;
        int incl = x + pre + carry_s;
        if (i < NN) g_off[i + 1] = incl;
        if (i == 0) g_off[0] = 0;
        __syncthreads();
        if (tid == 0) carry_s += wsum[31];
        __syncthreads();
    }
}

__global__ void k_fill() {
    int e = blockIdx.x * blockDim.x + threadIdx.x;
    if (e >= EE) return;
    int d = g_dst[e];
    int p = atomicAdd(&g_cur[d], 1);
    g_esrc[g_off[d] + p] = g_src[e];
}

// ---------------- layer 1 logits ----------------
__global__ void k_logits1(const float* __restrict__ as1, const float* __restrict__ ad1) {
    int n = blockIdx.x;
    int h = threadIdx.x >> 5, l = threadIdx.x & 31;
    float v0 = g_h1[(size_t)n * HIDD + h * DH + l];
    float v1 = g_h1[(size_t)n * HIDD + h * DH + 32 + l];
    float s = v0 * as1[h * DH + l] + v1 * as1[h * DH + 32 + l];
    float d = v0 * ad1[h * DH + l] + v1 * ad1[h * DH + 32 + l];
#pragma unroll
    for (int o = 16; o; o >>= 1) {
        s += __shfl_xor_sync(0xffffffffu, s, o);
        d += __shfl_xor_sync(0xffffffffu, d, o);
    }
    if (l == 0) { g_als1[n * NHEAD + h] = s; g_ald1[n * NHEAD + h] = d; }
}

// ---------------- layer 1 fused: softmax + aggregate + bias + LN + ELU ----------------
// warp per node (NN = 6250 * 8 exactly)
__global__ __launch_bounds__(256)
void k_csragg1(const float* __restrict__ b1, const float* __restrict__ g1,
               const float* __restrict__ be1) {
    int wid = threadIdx.x >> 5, lane = threadIdx.x & 31;
    int n = blockIdx.x * 8 + wid;
    int o0 = g_off[n], o1 = g_off[n + 1];
    int deg = o1 - o0;

    float aldn[NHEAD];
#pragma unroll
    for (int h = 0; h < NHEAD; h++) aldn[h] = g_ald1[n * NHEAD + h];

    float mx[NHEAD] = {-1e30f, -1e30f, -1e30f, -1e30f};
    for (int i = lane; i < deg; i += 32) {
        int s = g_esrc[o0 + i];
#pragma unroll
        for (int h = 0; h < NHEAD; h++) {
            float ev = g_als1[s * NHEAD + h] + aldn[h];
            ev = (ev >= 0.f) ? ev : NEG * ev;
            mx[h] = fmaxf(mx[h], ev);
        }
    }
#pragma unroll
    for (int h = 0; h < NHEAD; h++)
#pragma unroll
        for (int o = 16; o; o >>= 1)
            mx[h] = fmaxf(mx[h], __shfl_xor_sync(0xffffffffu, mx[h], o));

    float sm[NHEAD] = {0.f, 0.f, 0.f, 0.f};
    for (int i = lane; i < deg; i += 32) {
        int s = g_esrc[o0 + i];
#pragma unroll
        for (int h = 0; h < NHEAD; h++) {
            float ev = g_als1[s * NHEAD + h] + aldn[h];
            ev = (ev >= 0.f) ? ev : NEG * ev;
            sm[h] += expf(ev - mx[h]);
        }
    }
#pragma unroll
    for (int h = 0; h < NHEAD; h++)
#pragma unroll
        for (int o = 16; o; o >>= 1)
            sm[h] += __shfl_xor_sync(0xffffffffu, sm[h], o);

    float acc[8] = {0.f, 0.f, 0.f, 0.f, 0.f, 0.f, 0.f, 0.f};
    for (int i = 0; i < deg; i++) {
        int s = g_esrc[o0 + i];                 // uniform across warp
        float alh = 0.f;
        if (lane < NHEAD) {
            float ev = g_als1[s * NHEAD + lane] + aldn[lane];
            ev = (ev >= 0.f) ? ev : NEG * ev;
            alh = expf(ev - mx[lane]) / sm[lane];
        }
        float al[NHEAD];
#pragma unroll
        for (int h = 0; h < NHEAD; h++) al[h] = __shfl_sync(0xffffffffu, alh, h);
#pragma unroll
        for (int j = 0; j < 8; j++)
            acc[j] += g_h1[(size_t)s * HIDD + j * 32 + lane] * al[j >> 1];
    }

    // + bias, LayerNorm, ELU
    float sum = 0.f;
#pragma unroll
    for (int j = 0; j < 8; j++) { acc[j] += b1[j * 32 + lane]; sum += acc[j]; }
#pragma unroll
    for (int o = 16; o; o >>= 1) sum += __shfl_xor_sync(0xffffffffu, sum, o);
    float mu = sum * (1.f / HIDD);
    float s2 = 0.f;
#pragma unroll
    for (int j = 0; j < 8; j++) { acc[j] -= mu; s2 += acc[j] * acc[j]; }
#pragma unroll
    for (int o = 16; o; o >>= 1) s2 += __shfl_xor_sync(0xffffffffu, s2, o);
    float r = rsqrtf(s2 * (1.f / HIDD) + LNEPS);
#pragma unroll
    for (int j = 0; j < 8; j++) {
        float y = acc[j] * r * g1[j * 32 + lane] + be1[j * 32 + lane];
        g_agg1[(size_t)n * HIDD + j * 32 + lane] = (y > 0.f) ? y : expm1f(y);
    }
}

// ---------------- GEMM2: z = h2 @ W2  (128x64 tile, BK=16) ----------------
__global__ __launch_bounds__(256, 2)
void k_gemm2(const float* __restrict__ B) {
    __shared__ float As[16][128];
    __shared__ float Bs[16][64];
    const float* A = g_agg1;
    const int tid = threadIdx.x;
    const int tx = tid & 15, ty = tid >> 4;
    const int bm = blockIdx.y * 128;

    float acc[8][4];
#pragma unroll
    for (int m = 0; m < 8; m++)
#pragma unroll
        for (int j = 0; j < 4; j++) acc[m][j] = 0.f;

    float4 pa[2], pb;
#pragma unroll
    for (int i = 0; i < 2; i++) {
        int s = tid * 2 + i;
        int row = s >> 2, kc = (s & 3) * 4;
        int gr = bm + row;
        pa[i] = make_float4(0.f, 0.f, 0.f, 0.f);
        if (gr < NN) pa[i] = *(const float4*)&A[(size_t)gr * HIDD + kc];
    }
    { int kr = tid >> 4, nc = (tid & 15) * 4;
      pb = *(const float4*)&B[(size_t)kr * OUTD + nc]; }
#pragma unroll
    for (int i = 0; i < 2; i++) {
        int s = tid * 2 + i;
        int row = s >> 2, kc = (s & 3) * 4;
        As[kc + 0][row] = pa[i].x; As[kc + 1][row] = pa[i].y;
        As[kc + 2][row] = pa[i].z; As[kc + 3][row] = pa[i].w;
    }
    { int kr = tid >> 4, nc = (tid & 15) * 4; *(float4*)&Bs[kr][nc] = pb; }
    __syncthreads();

    for (int kt = 0; kt < 16; kt++) {
        if (kt < 15) {
            int k0 = (kt + 1) * 16;
#pragma unroll
            for (int i = 0; i < 2; i++) {
                int s = tid * 2 + i;
                int row = s >> 2, kc = (s & 3) * 4;
                int gr = bm + row;
                pa[i] = make_float4(0.f, 0.f, 0.f, 0.f);
                if (gr < NN) pa[i] = *(const float4*)&A[(size_t)gr * HIDD + k0 + kc];
            }
            { int kr = tid >> 4, nc = (tid & 15) * 4;
              pb = *(const float4*)&B[(size_t)(k0 + kr) * OUTD + nc]; }
        }
#pragma unroll
        for (int k = 0; k < 16; k++) {
            float4 b0 = *(const float4*)&Bs[k][tx * 4];
            float4 a0 = *(const float4*)&As[k][ty * 8];
            float4 a1 = *(const float4*)&As[k][ty * 8 + 4];
            float av[8] = {a0.x, a0.y, a0.z, a0.w, a1.x, a1.y, a1.z, a1.w};
            float bv[4] = {b0.x, b0.y, b0.z, b0.w};
#pragma unroll
            for (int m = 0; m < 8; m++)
#pragma unroll
                for (int j = 0; j < 4; j++)
                    acc[m][j] = fmaf(av[m], bv[j], acc[m][j]);
        }
        __syncthreads();
        if (kt < 15) {
#pragma unroll
            for (int i = 0; i < 2; i++) {
                int s = tid * 2 + i;
                int row = s >> 2, kc = (s & 3) * 4;
                As[kc + 0][row] = pa[i].x; As[kc + 1][row] = pa[i].y;
                As[kc + 2][row] = pa[i].z; As[kc + 3][row] = pa[i].w;
            }
            { int kr = tid >> 4, nc = (tid & 15) * 4; *(float4*)&Bs[kr][nc] = pb; }
        }
        __syncthreads();
    }

#pragma unroll
    for (int m = 0; m < 8; m++) {
        int gr = bm + ty * 8 + m;
        if (gr >= NN) continue;
        float4 v = make_float4(acc[m][0], acc[m][1], acc[m][2], acc[m][3]);
        *(float4*)&g_z[(size_t)gr * OUTD + tx * 4] = v;
    }
}

// ---------------- layer 2 logits ----------------
__global__ void k_logits2(const float* __restrict__ as2, const float* __restrict__ ad2) {
    int n = blockIdx.x * 4 + (threadIdx.x >> 5);
    if (n >= NN) return;
    int l = threadIdx.x & 31;
    float v0 = g_z[(size_t)n * OUTD + l];
    float v1 = g_z[(size_t)n * OUTD + 32 + l];
    float s = v0 * as2[l] + v1 * as2[32 + l];
    float d = v0 * ad2[l] + v1 * ad2[32 + l];
#pragma unroll
    for (int o = 16; o; o >>= 1) {
        s += __shfl_xor_sync(0xffffffffu, s, o);
        d += __shfl_xor_sync(0xffffffffu, d, o);
    }
    if (l == 0) { g_als2[n] = s; g_ald2[n] = d; }
}

// ---------------- layer 2 fused: softmax + aggregate + bias + LN -> out ----------------
__global__ __launch_bounds__(256)
void k_csragg2(const float* __restrict__ b2, const float* __restrict__ g2,
               const float* __restrict__ be2, float* __restrict__ out) {
    int wid = threadIdx.x >> 5, lane = threadIdx.x & 31;
    int n = blockIdx.x * 8 + wid;
    int o0 = g_off[n], o1 = g_off[n + 1];
    int deg = o1 - o0;

    float aldn = g_ald2[n];
    float mx = -1e30f;
    for (int i = lane; i < deg; i += 32) {
        int s = g_esrc[o0 + i];
        float ev = g_als2[s] + aldn;
        ev = (ev >= 0.f) ? ev : NEG * ev;
        mx = fmaxf(mx, ev);
    }
#pragma unroll
    for (int o = 16; o; o >>= 1) mx = fmaxf(mx, __shfl_xor_sync(0xffffffffu, mx, o));
    float sm = 0.f;
    for (int i = lane; i < deg; i += 32) {
        int s = g_esrc[o0 + i];
        float ev = g_als2[s] + aldn;
        ev = (ev >= 0.f) ? ev : NEG * ev;
        sm += expf(ev - mx);
    }
#pragma unroll
    for (int o = 16; o; o >>= 1) sm += __shfl_xor_sync(0xffffffffu, sm, o);

    float a0 = 0.f, a1 = 0.f;
    for (int i = 0; i < deg; i++) {
        int s = g_esrc[o0 + i];
        float alh = 0.f;
        if (lane == 0) {
            float ev = g_als2[s] + aldn;
            ev = (ev >= 0.f) ? ev : NEG * ev;
            alh = expf(ev - mx) / sm;
        }
        float al = __shfl_sync(0xffffffffu, alh, 0);
        a0 += g_z[(size_t)s * OUTD + lane] * al;
        a1 += g_z[(size_t)s * OUTD + 32 + lane] * al;
    }

    a0 += b2[lane];
    a1 += b2[32 + lane];
    float sum = a0 + a1;
#pragma unroll
    for (int o = 16; o; o >>= 1) sum += __shfl_xor_sync(0xffffffffu, sum, o);
    float mu = sum * (1.f / OUTD);
    a0 -= mu; a1 -= mu;
    float s2 = a0 * a0 + a1 * a1;
#pragma unroll
    for (int o = 16; o; o >>= 1) s2 += __shfl_xor_sync(0xffffffffu, s2, o);
    float r = rsqrtf(s2 * (1.f / OUTD) + LNEPS);
    out[(size_t)n * OUTD + lane]      = a0 * r * g2[lane] + be2[lane];
    out[(size_t)n * OUTD + 32 + lane] = a1 * r * g2[32 + lane] + be2[32 + lane];
}

// ---------------- launch ----------------
extern "C" void kernel_launch(void* const* d_in, const int* in_sizes, int n_in,
                              void* d_out, int out_size) {
    const float* x   = (const float*)d_in[0];
    const int*   ei  = (const int*)d_in[1];   // int32 or int64 (auto-detected)
    const int*   et  = (const int*)d_in[2];
    const float* emb = (const float*)d_in[3];
    const float* W1  = (const float*)d_in[4];
    const float* as1 = (const float*)d_in[5];
    const float* ad1 = (const float*)d_in[6];
    const float* b1  = (const float*)d_in[7];
    const float* g1  = (const float*)d_in[8];
    const float* be1 = (const float*)d_in[9];
    const float* W2  = (const float*)d_in[10];
    const float* as2 = (const float*)d_in[11];
    const float* ad2 = (const float*)d_in[12];
    const float* b2  = (const float*)d_in[13];
    const float* g2  = (const float*)d_in[14];
    const float* be2 = (const float*)d_in[15];
    float* out = (float*)d_out;

    k_init_embw<<<(NN + 255) / 256, 256>>>(emb, W1);   // 1
    k_detect<<<1, 256>>>(ei);                          // 2
    k_convwc<<<(EE + 255) / 256, 256>>>(ei, et);       // 3

    dim3 grid1(HIDD / 128, (NN + 127) / 128);
    k_gemm1<<<grid1, 256>>>(x, W1);                    // 4  <- profiler slot

    k_scan<<<1, 1024>>>();                             // 5
    k_fill<<<(EE + 255) / 256, 256>>>();               // 6
    k_logits1<<<NN, 128>>>(as1, ad1);                  // 7
    k_csragg1<<<NN / 8, 256>>>(b1, g1, be1);           // 8

    dim3 grid2(1, (NN + 127) / 128);
    k_gemm2<<<grid2, 256>>>(W2);                       // 9
    k_logits2<<<(NN + 3) / 4, 128>>>(as2, ad2);        // 10
    k_csragg2<<<NN / 8, 256>>>(b2, g2, be2, out);      // 11
}